// round 5
// baseline (speedup 1.0000x reference)
#include <cuda_runtime.h>

// BiologicalNormalization: 3 chained per-row LayerNorms (D=512), gathered
// per-sample affine params; trailing sigmoid-gated blend is the identity.
//
// R5: software-pipelined. Each warp owns 8 rows as 4 groups of 2, register
// prefetch of group k+1 overlaps compute of group k -> continuous DRAM issue.
// Params warp-shared via __ldg (L1). Streaming hints on x/out (.cs).

#define B_DIM 2048
#define S_DIM 128
#define D_DIM 512
#define THREADS 256
#define WARPS 8
#define RG 2                 // rows per group
#define GROUPS 4             // groups per warp -> 8 rows/warp, 64 rows/block
#define SPLIT 2              // blocks per sample

__global__ __launch_bounds__(THREADS, 2)
void bionorm_kernel(const float* __restrict__ x,
                    const int* __restrict__ pathway_ids,
                    const int* __restrict__ compartment_ids,
                    const int* __restrict__ cell_type_ids,
                    const float* __restrict__ pg, const float* __restrict__ pb,
                    const float* __restrict__ cg, const float* __restrict__ cb,
                    const float* __restrict__ tg, const float* __restrict__ tb,
                    float* __restrict__ out)
{
    const int blk = blockIdx.x;
    const int b = blk >> 1;           // sample
    const int half = blk & 1;
    const int warp = threadIdx.x >> 5;
    const int lane = threadIdx.x & 31;

    const int p_id = __ldg(pathway_ids + b);
    const int c_id = __ldg(compartment_ids + b);
    const int t_id = __ldg(cell_type_ids + b);

    const float4* __restrict__ gv[3] = {
        reinterpret_cast<const float4*>(pg + (size_t)p_id * D_DIM),
        reinterpret_cast<const float4*>(cg + (size_t)c_id * D_DIM),
        reinterpret_cast<const float4*>(tg + (size_t)t_id * D_DIM)
    };
    const float4* __restrict__ bv[3] = {
        reinterpret_cast<const float4*>(pb + (size_t)p_id * D_DIM),
        reinterpret_cast<const float4*>(cb + (size_t)c_id * D_DIM),
        reinterpret_cast<const float4*>(tb + (size_t)t_id * D_DIM)
    };

    const int s0 = half * 64 + warp * (RG * GROUPS);
    const size_t base = ((size_t)b * S_DIM + s0) * D_DIM;
    const float4* __restrict__ xr = reinterpret_cast<const float4*>(x + base);
    float4* __restrict__ orow = reinterpret_cast<float4*>(out + base);

    const float inv_d = 1.0f / (float)D_DIM;
    const float eps = 1e-5f;
    const int RQ = D_DIM / 4;         // float4 per row

    // Preload group 0 (2 rows, 8 LDG.128, streaming).
    float4 v[RG][4];
    #pragma unroll
    for (int r = 0; r < RG; r++)
        #pragma unroll
        for (int i = 0; i < 4; i++)
            v[r][i] = __ldcs(xr + r * RQ + lane + 32 * i);

    #pragma unroll
    for (int gidx = 0; gidx < GROUPS; gidx++) {
        // Prefetch next group while computing this one.
        float4 n[RG][4];
        if (gidx + 1 < GROUPS) {
            const float4* nx = xr + (gidx + 1) * RG * RQ;
            #pragma unroll
            for (int r = 0; r < RG; r++)
                #pragma unroll
                for (int i = 0; i < 4; i++)
                    n[r][i] = __ldcs(nx + r * RQ + lane + 32 * i);
        }

        #pragma unroll
        for (int p = 0; p < 3; p++) {
            float sum[RG], sq[RG];
            #pragma unroll
            for (int r = 0; r < RG; r++) {
                float s = 0.f, q = 0.f;
                #pragma unroll
                for (int i = 0; i < 4; i++) {
                    s += v[r][i].x + v[r][i].y + v[r][i].z + v[r][i].w;
                    q = fmaf(v[r][i].x, v[r][i].x, q);
                    q = fmaf(v[r][i].y, v[r][i].y, q);
                    q = fmaf(v[r][i].z, v[r][i].z, q);
                    q = fmaf(v[r][i].w, v[r][i].w, q);
                }
                sum[r] = s; sq[r] = q;
            }
            #pragma unroll
            for (int o = 16; o > 0; o >>= 1) {
                #pragma unroll
                for (int r = 0; r < RG; r++) {
                    sum[r] += __shfl_xor_sync(0xffffffffu, sum[r], o);
                    sq[r]  += __shfl_xor_sync(0xffffffffu, sq[r],  o);
                }
            }

            float mean[RG], rstd[RG];
            #pragma unroll
            for (int r = 0; r < RG; r++) {
                mean[r] = sum[r] * inv_d;
                const float var = fmaf(-mean[r], mean[r], sq[r] * inv_d);
                rstd[r] = rsqrtf(var + eps);
            }

            #pragma unroll
            for (int i = 0; i < 4; i++) {
                const float4 gg = __ldg(gv[p] + lane + 32 * i);
                const float4 bb = __ldg(bv[p] + lane + 32 * i);
                #pragma unroll
                for (int r = 0; r < RG; r++) {
                    v[r][i].x = fmaf((v[r][i].x - mean[r]) * rstd[r], gg.x, bb.x);
                    v[r][i].y = fmaf((v[r][i].y - mean[r]) * rstd[r], gg.y, bb.y);
                    v[r][i].z = fmaf((v[r][i].z - mean[r]) * rstd[r], gg.z, bb.z);
                    v[r][i].w = fmaf((v[r][i].w - mean[r]) * rstd[r], gg.w, bb.w);
                }
            }
        }

        // Store this group (streaming, fire-and-forget).
        float4* og = orow + gidx * RG * RQ;
        #pragma unroll
        for (int r = 0; r < RG; r++)
            #pragma unroll
            for (int i = 0; i < 4; i++)
                __stcs(og + r * RQ + lane + 32 * i, v[r][i]);

        if (gidx + 1 < GROUPS) {
            #pragma unroll
            for (int r = 0; r < RG; r++)
                #pragma unroll
                for (int i = 0; i < 4; i++)
                    v[r][i] = n[r][i];
        }
    }
}

extern "C" void kernel_launch(void* const* d_in, const int* in_sizes, int n_in,
                              void* d_out, int out_size)
{
    const float* x  = (const float*)d_in[0];
    const int* pid  = (const int*)d_in[1];
    const int* cid  = (const int*)d_in[2];
    const int* tid  = (const int*)d_in[3];
    const float* pg = (const float*)d_in[4];
    const float* pb = (const float*)d_in[5];
    const float* cg = (const float*)d_in[6];
    const float* cb = (const float*)d_in[7];
    const float* tg = (const float*)d_in[8];
    const float* tb = (const float*)d_in[9];
    // d_in[10] = W, d_in[11] = b : unused (gated blend is the identity)
    float* out = (float*)d_out;

    dim3 grid(B_DIM * SPLIT);
    dim3 block(THREADS);
    bionorm_kernel<<<grid, block>>>(x, pid, cid, tid,
                                    pg, pb, cg, cb, tg, tb, out);
}

// round 6
// speedup vs baseline: 1.6036x; 1.6036x over previous
#include <cuda_runtime.h>

// BiologicalNormalization: 3 chained per-row LayerNorms (D=512), gathered
// per-sample affine params; trailing sigmoid-gated blend is the identity.
//
// R6: R4 structure (front-batched loads, warp-local rows, no barriers) but
// ROWS=2 + __launch_bounds__(256,3) -> ~84 regs, 3 blocks/SM, 24 warps/SM.
// Latency hiding from warp count, not intra-warp pipelining (R5 lesson).
// Elementwise normalize folded to 2 FMAs via a=rstd, c=-mean*rstd.

#define B_DIM 2048
#define S_DIM 128
#define D_DIM 512
#define THREADS 256
#define WARPS 8
#define ROWS 2            // rows per warp -> 16 rows per block
#define SPLIT 8           // blocks per sample

__global__ __launch_bounds__(THREADS, 3)
void bionorm_kernel(const float* __restrict__ x,
                    const int* __restrict__ pathway_ids,
                    const int* __restrict__ compartment_ids,
                    const int* __restrict__ cell_type_ids,
                    const float* __restrict__ pg, const float* __restrict__ pb,
                    const float* __restrict__ cg, const float* __restrict__ cb,
                    const float* __restrict__ tg, const float* __restrict__ tb,
                    float* __restrict__ out)
{
    const int blk = blockIdx.x;
    const int b = blk >> 3;           // sample
    const int chunk = blk & 7;        // 16-row chunk within sample
    const int warp = threadIdx.x >> 5;
    const int lane = threadIdx.x & 31;

    const int p_id = __ldg(pathway_ids + b);
    const int c_id = __ldg(compartment_ids + b);
    const int t_id = __ldg(cell_type_ids + b);

    const int s0 = chunk * (WARPS * ROWS) + warp * ROWS;
    const size_t base = ((size_t)b * S_DIM + s0) * D_DIM;
    const float4* __restrict__ xr = reinterpret_cast<const float4*>(x + base);

    // Front-batched load of 2 full rows: 8 independent LDG.128.
    float4 v[ROWS][4];
    #pragma unroll
    for (int r = 0; r < ROWS; r++)
        #pragma unroll
        for (int i = 0; i < 4; i++)
            v[r][i] = xr[r * (D_DIM / 4) + lane + 32 * i];

    const float4* __restrict__ gv[3] = {
        reinterpret_cast<const float4*>(pg + (size_t)p_id * D_DIM),
        reinterpret_cast<const float4*>(cg + (size_t)c_id * D_DIM),
        reinterpret_cast<const float4*>(tg + (size_t)t_id * D_DIM)
    };
    const float4* __restrict__ bv[3] = {
        reinterpret_cast<const float4*>(pb + (size_t)p_id * D_DIM),
        reinterpret_cast<const float4*>(cb + (size_t)c_id * D_DIM),
        reinterpret_cast<const float4*>(tb + (size_t)t_id * D_DIM)
    };

    const float inv_d = 1.0f / (float)D_DIM;
    const float eps = 1e-5f;

    #pragma unroll
    for (int p = 0; p < 3; p++) {
        float sum[ROWS], sq[ROWS];
        #pragma unroll
        for (int r = 0; r < ROWS; r++) {
            float s = 0.f, q = 0.f;
            #pragma unroll
            for (int i = 0; i < 4; i++) {
                s += v[r][i].x + v[r][i].y + v[r][i].z + v[r][i].w;
                q = fmaf(v[r][i].x, v[r][i].x, q);
                q = fmaf(v[r][i].y, v[r][i].y, q);
                q = fmaf(v[r][i].z, v[r][i].z, q);
                q = fmaf(v[r][i].w, v[r][i].w, q);
            }
            sum[r] = s; sq[r] = q;
        }
        #pragma unroll
        for (int o = 16; o > 0; o >>= 1) {
            #pragma unroll
            for (int r = 0; r < ROWS; r++) {
                sum[r] += __shfl_xor_sync(0xffffffffu, sum[r], o);
                sq[r]  += __shfl_xor_sync(0xffffffffu, sq[r],  o);
            }
        }

        // a = rstd, c = -mean*rstd  ->  normalized = fma(v, a, c)
        float a[ROWS], c[ROWS];
        #pragma unroll
        for (int r = 0; r < ROWS; r++) {
            const float mean = sum[r] * inv_d;
            const float var = fmaf(-mean, mean, sq[r] * inv_d);
            a[r] = rsqrtf(var + eps);
            c[r] = -mean * a[r];
        }

        #pragma unroll
        for (int i = 0; i < 4; i++) {
            const float4 gg = __ldg(gv[p] + lane + 32 * i);
            const float4 bb = __ldg(bv[p] + lane + 32 * i);
            #pragma unroll
            for (int r = 0; r < ROWS; r++) {
                v[r][i].x = fmaf(fmaf(v[r][i].x, a[r], c[r]), gg.x, bb.x);
                v[r][i].y = fmaf(fmaf(v[r][i].y, a[r], c[r]), gg.y, bb.y);
                v[r][i].z = fmaf(fmaf(v[r][i].z, a[r], c[r]), gg.z, bb.z);
                v[r][i].w = fmaf(fmaf(v[r][i].w, a[r], c[r]), gg.w, bb.w);
            }
        }
    }

    float4* __restrict__ orow = reinterpret_cast<float4*>(out + base);
    #pragma unroll
    for (int r = 0; r < ROWS; r++)
        #pragma unroll
        for (int i = 0; i < 4; i++)
            orow[r * (D_DIM / 4) + lane + 32 * i] = v[r][i];
}

extern "C" void kernel_launch(void* const* d_in, const int* in_sizes, int n_in,
                              void* d_out, int out_size)
{
    const float* x  = (const float*)d_in[0];
    const int* pid  = (const int*)d_in[1];
    const int* cid  = (const int*)d_in[2];
    const int* tid  = (const int*)d_in[3];
    const float* pg = (const float*)d_in[4];
    const float* pb = (const float*)d_in[5];
    const float* cg = (const float*)d_in[6];
    const float* cb = (const float*)d_in[7];
    const float* tg = (const float*)d_in[8];
    const float* tb = (const float*)d_in[9];
    // d_in[10] = W, d_in[11] = b : unused (gated blend is the identity)
    float* out = (float*)d_out;

    dim3 grid(B_DIM * SPLIT);
    dim3 block(THREADS);
    bionorm_kernel<<<grid, block>>>(x, pid, cid, tid,
                                    pg, pb, cg, cb, tg, tb, out);
}

// round 7
// speedup vs baseline: 1.7019x; 1.0613x over previous
#include <cuda_runtime.h>

// BiologicalNormalization: 3 chained per-row LayerNorms (D=512), gathered
// per-sample affine params; trailing sigmoid-gated blend is the identity.
//
// R7: R6 shape (ROWS=2 per warp, warp-local, no barriers) at higher
// occupancy: 128-thread blocks, __launch_bounds__(128,7) -> 72-reg cap,
// 28 warps/SM (43.75% occ). Latency hiding purely from warp count.

#define B_DIM 2048
#define S_DIM 128
#define D_DIM 512
#define THREADS 128
#define WARPS 4
#define ROWS 2            // rows per warp -> 8 rows per block
#define SPLIT 16          // blocks per sample

__global__ __launch_bounds__(THREADS, 7)
void bionorm_kernel(const float* __restrict__ x,
                    const int* __restrict__ pathway_ids,
                    const int* __restrict__ compartment_ids,
                    const int* __restrict__ cell_type_ids,
                    const float* __restrict__ pg, const float* __restrict__ pb,
                    const float* __restrict__ cg, const float* __restrict__ cb,
                    const float* __restrict__ tg, const float* __restrict__ tb,
                    float* __restrict__ out)
{
    const int blk = blockIdx.x;
    const int b = blk >> 4;           // sample
    const int chunk = blk & 15;       // 8-row chunk within sample
    const int warp = threadIdx.x >> 5;
    const int lane = threadIdx.x & 31;

    const int p_id = __ldg(pathway_ids + b);
    const int c_id = __ldg(compartment_ids + b);
    const int t_id = __ldg(cell_type_ids + b);

    const int s0 = chunk * (WARPS * ROWS) + warp * ROWS;
    const size_t base = ((size_t)b * S_DIM + s0) * D_DIM;
    const float4* __restrict__ xr = reinterpret_cast<const float4*>(x + base);

    // Front-batched load of 2 full rows: 8 independent LDG.128.
    float4 v[ROWS][4];
    #pragma unroll
    for (int r = 0; r < ROWS; r++)
        #pragma unroll
        for (int i = 0; i < 4; i++)
            v[r][i] = xr[r * (D_DIM / 4) + lane + 32 * i];

    const float inv_d = 1.0f / (float)D_DIM;
    const float eps = 1e-5f;

    #pragma unroll
    for (int p = 0; p < 3; p++) {
        // Param pointers rematerialized per pass (constant-bank bases),
        // keeps live address registers low for the 72-reg cap.
        const float4* gvp;
        const float4* bvp;
        if (p == 0) {
            gvp = reinterpret_cast<const float4*>(pg + (size_t)p_id * D_DIM);
            bvp = reinterpret_cast<const float4*>(pb + (size_t)p_id * D_DIM);
        } else if (p == 1) {
            gvp = reinterpret_cast<const float4*>(cg + (size_t)c_id * D_DIM);
            bvp = reinterpret_cast<const float4*>(cb + (size_t)c_id * D_DIM);
        } else {
            gvp = reinterpret_cast<const float4*>(tg + (size_t)t_id * D_DIM);
            bvp = reinterpret_cast<const float4*>(tb + (size_t)t_id * D_DIM);
        }

        float sum[ROWS], sq[ROWS];
        #pragma unroll
        for (int r = 0; r < ROWS; r++) {
            float s = 0.f, q = 0.f;
            #pragma unroll
            for (int i = 0; i < 4; i++) {
                s += v[r][i].x + v[r][i].y + v[r][i].z + v[r][i].w;
                q = fmaf(v[r][i].x, v[r][i].x, q);
                q = fmaf(v[r][i].y, v[r][i].y, q);
                q = fmaf(v[r][i].z, v[r][i].z, q);
                q = fmaf(v[r][i].w, v[r][i].w, q);
            }
            sum[r] = s; sq[r] = q;
        }
        #pragma unroll
        for (int o = 16; o > 0; o >>= 1) {
            #pragma unroll
            for (int r = 0; r < ROWS; r++) {
                sum[r] += __shfl_xor_sync(0xffffffffu, sum[r], o);
                sq[r]  += __shfl_xor_sync(0xffffffffu, sq[r],  o);
            }
        }

        // a = rstd, c = -mean*rstd  ->  normalized = fma(v, a, c)
        float a[ROWS], c[ROWS];
        #pragma unroll
        for (int r = 0; r < ROWS; r++) {
            const float mean = sum[r] * inv_d;
            const float var = fmaf(-mean, mean, sq[r] * inv_d);
            a[r] = rsqrtf(var + eps);
            c[r] = -mean * a[r];
        }

        #pragma unroll
        for (int i = 0; i < 4; i++) {
            const float4 gg = __ldg(gvp + lane + 32 * i);
            const float4 bb = __ldg(bvp + lane + 32 * i);
            #pragma unroll
            for (int r = 0; r < ROWS; r++) {
                v[r][i].x = fmaf(fmaf(v[r][i].x, a[r], c[r]), gg.x, bb.x);
                v[r][i].y = fmaf(fmaf(v[r][i].y, a[r], c[r]), gg.y, bb.y);
                v[r][i].z = fmaf(fmaf(v[r][i].z, a[r], c[r]), gg.z, bb.z);
                v[r][i].w = fmaf(fmaf(v[r][i].w, a[r], c[r]), gg.w, bb.w);
            }
        }
    }

    float4* __restrict__ orow = reinterpret_cast<float4*>(out + base);
    #pragma unroll
    for (int r = 0; r < ROWS; r++)
        #pragma unroll
        for (int i = 0; i < 4; i++)
            orow[r * (D_DIM / 4) + lane + 32 * i] = v[r][i];
}

extern "C" void kernel_launch(void* const* d_in, const int* in_sizes, int n_in,
                              void* d_out, int out_size)
{
    const float* x  = (const float*)d_in[0];
    const int* pid  = (const int*)d_in[1];
    const int* cid  = (const int*)d_in[2];
    const int* tid  = (const int*)d_in[3];
    const float* pg = (const float*)d_in[4];
    const float* pb = (const float*)d_in[5];
    const float* cg = (const float*)d_in[6];
    const float* cb = (const float*)d_in[7];
    const float* tg = (const float*)d_in[8];
    const float* tb = (const float*)d_in[9];
    // d_in[10] = W, d_in[11] = b : unused (gated blend is the identity)
    float* out = (float*)d_out;

    dim3 grid(B_DIM * SPLIT);
    dim3 block(THREADS);
    bionorm_kernel<<<grid, block>>>(x, pid, cid, tid,
                                    pg, pb, cg, cb, tg, tb, out);
}